// round 16
// baseline (speedup 1.0000x reference)
#include <cuda_runtime.h>
#include <math.h>

#define BB 8
#define TT 256
#define DD 12
#define HH 4
#define HD 3
#define NTOK (BB*TT)

// scratch (no cudaMalloc allowed)
__device__ float g_kT[BB * HH * HD * TT]; // [b][h][i][t] key-major rows (float4-aligned)
__device__ float g_vT[BB * HH * HD * TT];

// ---------------------------------------------------------------------------
// K1: K/V projection only (Q lives in the consumer's PDL overlap window).
// 16 tokens/block x 12 dims = 192 threads. Signals dependents immediately.
// ---------------------------------------------------------------------------
__global__ __launch_bounds__(192)
void kv_kernel(const float* __restrict__ x,
               const float* __restrict__ wk, const float* __restrict__ wv,
               const float* __restrict__ bk, const float* __restrict__ bv)
{
    asm volatile("griddepcontrol.launch_dependents;");

    const int tid = threadIdx.x;
    const int n0  = blockIdx.x * 16;

    __shared__ float xs[16][DD + 1];
    __shared__ float wks[DD * DD], wvs[DD * DD];
    __shared__ float bs[2 * DD];

    if (tid < DD * DD) { wks[tid] = wk[tid]; wvs[tid] = wv[tid]; }
    if (tid < DD) { bs[tid] = bk[tid]; bs[DD + tid] = bv[tid]; }
    {   // coalesced: 192 floats = 16 rows x 12
        const int r = tid / DD, c = tid - r * DD;
        xs[r][c] = x[n0 * DD + tid];
    }
    __syncthreads();

    const int t = tid / DD;
    const int d = tid - t * DD;
    const int n = n0 + t;

    float ak = bs[d], av = bs[DD + d];
    #pragma unroll
    for (int j = 0; j < DD; j++) {
        const float xj = xs[t][j];
        ak = fmaf(xj, wks[d * DD + j], ak);
        av = fmaf(xj, wvs[d * DD + j], av);
    }

    const int b = n >> 8, tt = n & 255;
    const int h = d / HD, i = d - h * HD;
    const int base = ((b * HH + h) * HD + i) * TT + tt;
    g_kT[base] = ak;
    g_vT[base] = av;
}

// ---------------------------------------------------------------------------
// K2: fused Q-projection + attention + output projection + quantum expvals.
// Geometry: 512 blocks x 128 thr (measured-fastest post-wait shape).
// Block = 4 consecutive tokens; warp h = head h handles ALL 4 tokens.
// PDL: staging + Q projection run BEFORE griddepcontrol.wait.
// q pre-scaled by log2e/sqrt(3) -> softmax weights via exp2f (bare MUFU).
// Two-phase: accumulate all 4 tokens, then 4 INTERLEAVED shfl reductions.
//   out[k] = prod_{j=0..k} cos(phi_j) (k>=1) ; out[0] = prod_{j=1..11}
//   phi = ctx @ wo.T + bo + theta   (quantum circuit collapsed analytically)
// ---------------------------------------------------------------------------
__global__ __launch_bounds__(128)
void attn_quantum_kernel(const float* __restrict__ x,
                         const float* __restrict__ wq,
                         const float* __restrict__ bq,
                         const float* __restrict__ wo,
                         const float* __restrict__ bo,
                         const float* __restrict__ theta,
                         float* __restrict__ out)
{
    const int tid  = threadIdx.x;
    const int h    = tid >> 5;          // warp = head
    const int lane = tid & 31;
    const int n0   = blockIdx.x * 4;    // 4 tokens, same batch (4 | 256)
    const int b    = n0 >> 8;

    __shared__ float xs[4][DD + 1];           // this block's 4 x rows
    __shared__ float wqs[DD * DD], wos[DD * DD];
    __shared__ float bqs[DD], bts[DD];
    __shared__ float ctxs[4][DD + 1];

    // ---- pre-wait preamble: stage independent inputs (overlaps producer) ----
    if (tid < 4 * DD) {                       // 48 floats, coalesced
        const int r = tid / DD, c = tid - r * DD;
        xs[r][c] = x[n0 * DD + tid];
    }
    if (tid < DD * DD - 128) { wqs[128 + tid] = wq[128 + tid]; wos[128 + tid] = wo[128 + tid]; }
    wqs[tid] = wq[tid]; wos[tid] = wo[tid];
    if (tid < DD) { bqs[tid] = bq[tid]; bts[tid] = bo[tid] + theta[tid]; }
    __syncthreads();

    // ---- pre-wait Q projection, warp-local (still overlapped) ----
    // lane e < 12: token e/3, head-dim i = e%3  ->  qv
    // pre-scaled by log2e/sqrt(hd): score lands directly in log2 domain.
    float qv;
    {
        const int e  = (lane < 12) ? lane : 0;
        const int tq = e / 3;
        const int d  = h * HD + (e - tq * 3);
        float a = bqs[d];
        #pragma unroll
        for (int j = 0; j < DD; j++) a = fmaf(xs[tq][j], wqs[d * DD + j], a);
        qv = a * 0.83297768f;                 // log2(e)/sqrt(3)
    }

    asm volatile("griddepcontrol.wait;");

    // ---- K/V for head h: 8 keys per lane, loaded ONCE for 4 queries ----
    const float4* kb4 = (const float4*)(g_kT + (b * HH + h) * HD * TT);
    const float4* vb4 = (const float4*)(g_vT + (b * HH + h) * HD * TT);
    const float4 kxa = kb4[lane],       kxb = kb4[32 + lane];
    const float4 kya = kb4[64 + lane],  kyb = kb4[96 + lane];
    const float4 kza = kb4[128 + lane], kzb = kb4[160 + lane];
    const float4 vxa = vb4[lane],       vxb = vb4[32 + lane];
    const float4 vya = vb4[64 + lane],  vyb = vb4[96 + lane];
    const float4 vza = vb4[128 + lane], vzb = vb4[160 + lane];

    float L[4], A0[4], A1[4], A2[4];

    // ---- phase A: accumulate all 4 tokens (no reductions yet) ----
    #pragma unroll
    for (int t = 0; t < 4; t++) {
        const float q0 = __shfl_sync(0xFFFFFFFFu, qv, t * 3 + 0);
        const float q1 = __shfl_sync(0xFFFFFFFFu, qv, t * 3 + 1);
        const float q2 = __shfl_sync(0xFFFFFFFFu, qv, t * 3 + 2);

        float l = 0.f, a0 = 0.f, a1 = 0.f, a2 = 0.f;
        float p;
        p = exp2f(q0*kxa.x + q1*kya.x + q2*kza.x);
        l += p; a0 = fmaf(p, vxa.x, a0); a1 = fmaf(p, vya.x, a1); a2 = fmaf(p, vza.x, a2);
        p = exp2f(q0*kxa.y + q1*kya.y + q2*kza.y);
        l += p; a0 = fmaf(p, vxa.y, a0); a1 = fmaf(p, vya.y, a1); a2 = fmaf(p, vza.y, a2);
        p = exp2f(q0*kxa.z + q1*kya.z + q2*kza.z);
        l += p; a0 = fmaf(p, vxa.z, a0); a1 = fmaf(p, vya.z, a1); a2 = fmaf(p, vza.z, a2);
        p = exp2f(q0*kxa.w + q1*kya.w + q2*kza.w);
        l += p; a0 = fmaf(p, vxa.w, a0); a1 = fmaf(p, vya.w, a1); a2 = fmaf(p, vza.w, a2);
        p = exp2f(q0*kxb.x + q1*kyb.x + q2*kzb.x);
        l += p; a0 = fmaf(p, vxb.x, a0); a1 = fmaf(p, vyb.x, a1); a2 = fmaf(p, vzb.x, a2);
        p = exp2f(q0*kxb.y + q1*kyb.y + q2*kzb.y);
        l += p; a0 = fmaf(p, vxb.y, a0); a1 = fmaf(p, vyb.y, a1); a2 = fmaf(p, vzb.y, a2);
        p = exp2f(q0*kxb.z + q1*kyb.z + q2*kzb.z);
        l += p; a0 = fmaf(p, vxb.z, a0); a1 = fmaf(p, vyb.z, a1); a2 = fmaf(p, vzb.z, a2);
        p = exp2f(q0*kxb.w + q1*kyb.w + q2*kzb.w);
        l += p; a0 = fmaf(p, vxb.w, a0); a1 = fmaf(p, vyb.w, a1); a2 = fmaf(p, vzb.w, a2);
        L[t] = l; A0[t] = a0; A1[t] = a1; A2[t] = a2;
    }

    // ---- phase B: 4 interleaved reductions (16-way then 4-way shfl ILP) ----
    #pragma unroll
    for (int off = 16; off >= 8; off >>= 1) {
        #pragma unroll
        for (int t = 0; t < 4; t++) {
            L[t]  += __shfl_xor_sync(0xFFFFFFFFu, L[t],  off);
            A0[t] += __shfl_xor_sync(0xFFFFFFFFu, A0[t], off);
            A1[t] += __shfl_xor_sync(0xFFFFFFFFu, A1[t], off);
            A2[t] += __shfl_xor_sync(0xFFFFFFFFu, A2[t], off);
        }
    }
    float v[4];
    #pragma unroll
    for (int t = 0; t < 4; t++)
        v[t] = (lane < 8) ? L[t] : (lane < 16) ? A0[t] : (lane < 24) ? A1[t] : A2[t];
    #pragma unroll
    for (int off = 4; off >= 1; off >>= 1) {
        #pragma unroll
        for (int t = 0; t < 4; t++)
            v[t] += __shfl_xor_sync(0xFFFFFFFFu, v[t], off);
    }
    #pragma unroll
    for (int t = 0; t < 4; t++) {
        const float ltot = __shfl_sync(0xFFFFFFFFu, v[t], 0);
        if ((lane & 7) == 0 && lane != 0)
            ctxs[t][h * HD + (lane >> 3) - 1] = __fdividef(v[t], ltot);
    }
    __syncthreads();

    // ---- tail: warp t handles token t (lanes 0..11 active math) ----
    {
        const int t = h;                 // 4 warps -> 4 tokens
        const int w = lane;
        float c = 1.0f;
        if (w < DD) {
            float a = bts[w];
            #pragma unroll
            for (int j = 0; j < DD; j++) a = fmaf(ctxs[t][j], wos[w * DD + j], a);
            c = __cosf(a);
        }
        // inclusive product scan: d_0 = 1, d_w = c_w (1<=w<12) -> S_w = c_1..c_w
        float d = (w >= 1 && w < DD) ? c : 1.0f;
        #pragma unroll
        for (int off = 1; off <= 8; off <<= 1) {
            const float s = __shfl_up_sync(0xFFFFFFFFu, d, off);
            if (lane >= off) d *= s;
        }
        const float c0  = __shfl_sync(0xFFFFFFFFu, c, 0);
        const float s11 = __shfl_sync(0xFFFFFFFFu, d, 11);
        if (w < DD)
            out[(n0 + t) * DD + w] = (w == 0) ? s11 : c0 * d;
    }
}

extern "C" void kernel_launch(void* const* d_in, const int* in_sizes, int n_in,
                              void* d_out, int out_size)
{
    const float* x     = (const float*)d_in[0];
    const float* wq    = (const float*)d_in[1];
    const float* wk    = (const float*)d_in[2];
    const float* wv    = (const float*)d_in[3];
    const float* bq    = (const float*)d_in[4];
    const float* bk    = (const float*)d_in[5];
    const float* bv    = (const float*)d_in[6];
    const float* wo    = (const float*)d_in[7];
    const float* bo    = (const float*)d_in[8];
    const float* theta = (const float*)d_in[9];
    float* out = (float*)d_out;

    kv_kernel<<<NTOK / 16, 192>>>(x, wk, wv, bk, bv);

    // PDL launch: overlap this grid's ramp + preamble + Q projection with kv
    cudaLaunchConfig_t cfg = {};
    cfg.gridDim  = dim3(NTOK / 4, 1, 1);
    cfg.blockDim = dim3(128, 1, 1);
    cfg.dynamicSmemBytes = 0;
    cfg.stream = 0;   // same (capture) stream as the <<<>>> launch above
    cudaLaunchAttribute attr[1];
    attr[0].id = cudaLaunchAttributeProgrammaticStreamSerialization;
    attr[0].val.programmaticStreamSerializationAllowed = 1;
    cfg.attrs = attr;
    cfg.numAttrs = 1;
    cudaLaunchKernelEx(&cfg, attn_quantum_kernel, x, wq, bq, wo, bo, theta, out);
}

// round 17
// speedup vs baseline: 1.0602x; 1.0602x over previous
#include <cuda_runtime.h>
#include <math.h>

#define BB 8
#define TT 256
#define DD 12
#define HH 4
#define HD 3
#define NTOK (BB*TT)

// scratch (no cudaMalloc allowed)
__device__ float g_kT[BB * HH * HD * TT]; // [b][h][i][t] key-major rows (float4-aligned)
__device__ float g_vT[BB * HH * HD * TT];

// ---------------------------------------------------------------------------
// K1: K/V projection only (Q lives in the consumer's PDL overlap window).
// 16 tokens/block x 12 dims = 192 threads. Signals dependents immediately.
// ---------------------------------------------------------------------------
__global__ __launch_bounds__(192)
void kv_kernel(const float* __restrict__ x,
               const float* __restrict__ wk, const float* __restrict__ wv,
               const float* __restrict__ bk, const float* __restrict__ bv)
{
    asm volatile("griddepcontrol.launch_dependents;");

    const int tid = threadIdx.x;
    const int n0  = blockIdx.x * 16;

    __shared__ float xs[16][DD + 1];
    __shared__ float wks[DD * DD], wvs[DD * DD];
    __shared__ float bs[2 * DD];

    if (tid < DD * DD) { wks[tid] = wk[tid]; wvs[tid] = wv[tid]; }
    if (tid < DD) { bs[tid] = bk[tid]; bs[DD + tid] = bv[tid]; }
    {   // coalesced: 192 floats = 16 rows x 12
        const int r = tid / DD, c = tid - r * DD;
        xs[r][c] = x[n0 * DD + tid];
    }
    __syncthreads();

    const int t = tid / DD;
    const int d = tid - t * DD;
    const int n = n0 + t;

    float ak = bs[d], av = bs[DD + d];
    #pragma unroll
    for (int j = 0; j < DD; j++) {
        const float xj = xs[t][j];
        ak = fmaf(xj, wks[d * DD + j], ak);
        av = fmaf(xj, wvs[d * DD + j], av);
    }

    const int b = n >> 8, tt = n & 255;
    const int h = d / HD, i = d - h * HD;
    const int base = ((b * HH + h) * HD + i) * TT + tt;
    g_kT[base] = ak;
    g_vT[base] = av;
}

// ---------------------------------------------------------------------------
// K2: fused Q-projection + attention + output projection + quantum expvals.
// Geometry: 512 blocks x 128 thr (measured-fastest post-wait shape).
// Block = 4 consecutive tokens; warp h = head h handles ALL 4 tokens (K/V in
// registers, 4x reuse). PDL: staging + Q projection BEFORE griddepcontrol.wait.
// q pre-scaled by log2e/sqrt(3) -> softmax weights via exp2f (bare MUFU.EX2,
// removes 32 FMULs/lane from the exp critical path). No-max softmax (scores
// O(10), fp32-safe). R15's serial per-token reductions (low register
// pressure — the R16 interleaved variant regressed via reg pressure).
//   out[k] = prod_{j=0..k} cos(phi_j) (k>=1) ; out[0] = prod_{j=1..11}
//   phi = ctx @ wo.T + bo + theta   (quantum circuit collapsed analytically)
// ---------------------------------------------------------------------------
__global__ __launch_bounds__(128)
void attn_quantum_kernel(const float* __restrict__ x,
                         const float* __restrict__ wq,
                         const float* __restrict__ bq,
                         const float* __restrict__ wo,
                         const float* __restrict__ bo,
                         const float* __restrict__ theta,
                         float* __restrict__ out)
{
    const int tid  = threadIdx.x;
    const int h    = tid >> 5;          // warp = head
    const int lane = tid & 31;
    const int n0   = blockIdx.x * 4;    // 4 tokens, same batch (4 | 256)
    const int b    = n0 >> 8;

    __shared__ float xs[4][DD + 1];           // this block's 4 x rows
    __shared__ float wqs[DD * DD], wos[DD * DD];
    __shared__ float bqs[DD], bts[DD];
    __shared__ float ctxs[4][DD + 1];

    // ---- pre-wait preamble: stage independent inputs (overlaps producer) ----
    if (tid < 4 * DD) {                       // 48 floats, coalesced
        const int r = tid / DD, c = tid - r * DD;
        xs[r][c] = x[n0 * DD + tid];
    }
    if (tid < DD * DD - 128) { wqs[128 + tid] = wq[128 + tid]; wos[128 + tid] = wo[128 + tid]; }
    wqs[tid] = wq[tid]; wos[tid] = wo[tid];
    if (tid < DD) { bqs[tid] = bq[tid]; bts[tid] = bo[tid] + theta[tid]; }
    __syncthreads();

    // ---- pre-wait Q projection, warp-local (still overlapped) ----
    // lane e < 12: token e/3, head-dim i = e%3  ->  qv
    // pre-scaled by log2(e)/sqrt(hd): scores land directly in log2 domain.
    float qv;
    {
        const int e  = (lane < 12) ? lane : 0;
        const int tq = e / 3;
        const int d  = h * HD + (e - tq * 3);
        float a = bqs[d];
        #pragma unroll
        for (int j = 0; j < DD; j++) a = fmaf(xs[tq][j], wqs[d * DD + j], a);
        qv = a * 0.83297768f;                 // log2(e)/sqrt(3)
    }

    asm volatile("griddepcontrol.wait;");

    // ---- K/V for head h: 8 keys per lane, loaded ONCE for 4 queries ----
    const float4* kb4 = (const float4*)(g_kT + (b * HH + h) * HD * TT);
    const float4* vb4 = (const float4*)(g_vT + (b * HH + h) * HD * TT);
    const float4 kxa = kb4[lane],       kxb = kb4[32 + lane];
    const float4 kya = kb4[64 + lane],  kyb = kb4[96 + lane];
    const float4 kza = kb4[128 + lane], kzb = kb4[160 + lane];
    const float4 vxa = vb4[lane],       vxb = vb4[32 + lane];
    const float4 vya = vb4[64 + lane],  vyb = vb4[96 + lane];
    const float4 vza = vb4[128 + lane], vzb = vb4[160 + lane];

    #pragma unroll
    for (int t = 0; t < 4; t++) {
        const float q0 = __shfl_sync(0xFFFFFFFFu, qv, t * 3 + 0);
        const float q1 = __shfl_sync(0xFFFFFFFFu, qv, t * 3 + 1);
        const float q2 = __shfl_sync(0xFFFFFFFFu, qv, t * 3 + 2);

        float l = 0.f, a0 = 0.f, a1 = 0.f, a2 = 0.f;
        {   // inline exp2 -> accumulate
            float p;
            p = exp2f(q0*kxa.x + q1*kya.x + q2*kza.x);
            l += p; a0 = fmaf(p, vxa.x, a0); a1 = fmaf(p, vya.x, a1); a2 = fmaf(p, vza.x, a2);
            p = exp2f(q0*kxa.y + q1*kya.y + q2*kza.y);
            l += p; a0 = fmaf(p, vxa.y, a0); a1 = fmaf(p, vya.y, a1); a2 = fmaf(p, vza.y, a2);
            p = exp2f(q0*kxa.z + q1*kya.z + q2*kza.z);
            l += p; a0 = fmaf(p, vxa.z, a0); a1 = fmaf(p, vya.z, a1); a2 = fmaf(p, vza.z, a2);
            p = exp2f(q0*kxa.w + q1*kya.w + q2*kza.w);
            l += p; a0 = fmaf(p, vxa.w, a0); a1 = fmaf(p, vya.w, a1); a2 = fmaf(p, vza.w, a2);
            p = exp2f(q0*kxb.x + q1*kyb.x + q2*kzb.x);
            l += p; a0 = fmaf(p, vxb.x, a0); a1 = fmaf(p, vyb.x, a1); a2 = fmaf(p, vzb.x, a2);
            p = exp2f(q0*kxb.y + q1*kyb.y + q2*kzb.y);
            l += p; a0 = fmaf(p, vxb.y, a0); a1 = fmaf(p, vyb.y, a1); a2 = fmaf(p, vzb.y, a2);
            p = exp2f(q0*kxb.z + q1*kyb.z + q2*kzb.z);
            l += p; a0 = fmaf(p, vxb.z, a0); a1 = fmaf(p, vyb.z, a1); a2 = fmaf(p, vzb.z, a2);
            p = exp2f(q0*kxb.w + q1*kyb.w + q2*kzb.w);
            l += p; a0 = fmaf(p, vxb.w, a0); a1 = fmaf(p, vyb.w, a1); a2 = fmaf(p, vzb.w, a2);
        }

        // split reduction: 2 butterfly levels on all 4, select by lane group,
        // 3 butterfly levels on one value.
        #pragma unroll
        for (int off = 16; off >= 8; off >>= 1) {
            l  += __shfl_xor_sync(0xFFFFFFFFu, l,  off);
            a0 += __shfl_xor_sync(0xFFFFFFFFu, a0, off);
            a1 += __shfl_xor_sync(0xFFFFFFFFu, a1, off);
            a2 += __shfl_xor_sync(0xFFFFFFFFu, a2, off);
        }
        float v = (lane < 8) ? l : (lane < 16) ? a0 : (lane < 24) ? a1 : a2;
        #pragma unroll
        for (int off = 4; off >= 1; off >>= 1)
            v += __shfl_xor_sync(0xFFFFFFFFu, v, off);
        // lanes 0-7: total l ; 8-15: a0 ; 16-23: a1 ; 24-31: a2
        const float ltot = __shfl_sync(0xFFFFFFFFu, v, 0);
        if ((lane & 7) == 0 && lane != 0)
            ctxs[t][h * HD + (lane >> 3) - 1] = __fdividef(v, ltot);
    }
    __syncthreads();

    // ---- tail: warp t handles token t (lanes 0..11 active math) ----
    {
        const int t = h;                 // 4 warps -> 4 tokens
        const int w = lane;
        float c = 1.0f;
        if (w < DD) {
            float a = bts[w];
            #pragma unroll
            for (int j = 0; j < DD; j++) a = fmaf(ctxs[t][j], wos[w * DD + j], a);
            c = __cosf(a);
        }
        // inclusive product scan: d_0 = 1, d_w = c_w (1<=w<12) -> S_w = c_1..c_w
        float d = (w >= 1 && w < DD) ? c : 1.0f;
        #pragma unroll
        for (int off = 1; off <= 8; off <<= 1) {
            const float s = __shfl_up_sync(0xFFFFFFFFu, d, off);
            if (lane >= off) d *= s;
        }
        const float c0  = __shfl_sync(0xFFFFFFFFu, c, 0);
        const float s11 = __shfl_sync(0xFFFFFFFFu, d, 11);
        if (w < DD)
            out[(n0 + t) * DD + w] = (w == 0) ? s11 : c0 * d;
    }
}

extern "C" void kernel_launch(void* const* d_in, const int* in_sizes, int n_in,
                              void* d_out, int out_size)
{
    const float* x     = (const float*)d_in[0];
    const float* wq    = (const float*)d_in[1];
    const float* wk    = (const float*)d_in[2];
    const float* wv    = (const float*)d_in[3];
    const float* bq    = (const float*)d_in[4];
    const float* bk    = (const float*)d_in[5];
    const float* bv    = (const float*)d_in[6];
    const float* wo    = (const float*)d_in[7];
    const float* bo    = (const float*)d_in[8];
    const float* theta = (const float*)d_in[9];
    float* out = (float*)d_out;

    kv_kernel<<<NTOK / 16, 192>>>(x, wk, wv, bk, bv);

    // PDL launch: overlap this grid's ramp + preamble + Q projection with kv
    cudaLaunchConfig_t cfg = {};
    cfg.gridDim  = dim3(NTOK / 4, 1, 1);
    cfg.blockDim = dim3(128, 1, 1);
    cfg.dynamicSmemBytes = 0;
    cfg.stream = 0;   // same (capture) stream as the <<<>>> launch above
    cudaLaunchAttribute attr[1];
    attr[0].id = cudaLaunchAttributeProgrammaticStreamSerialization;
    attr[0].val.programmaticStreamSerializationAllowed = 1;
    cfg.attrs = attr;
    cfg.numAttrs = 1;
    cudaLaunchKernelEx(&cfg, attn_quantum_kernel, x, wq, bq, wo, bo, theta, out);
}